// round 1
// baseline (speedup 1.0000x reference)
#include <cuda_runtime.h>
#include <math.h>

#define BB 16
#define L1 32
#define L2 128
#define DEC 512
#define MEMD 512
#define TOPN 50

// Scratch (allocation-free rule: __device__ globals)
__device__ float g_f1[BB * DEC];
__device__ float g_f2[BB * DEC];
__device__ float g_doc_score[BB * L1];
__device__ float g_doc_attn[BB * L1];

// ---------------------------------------------------------------------------
// Kernel A: f1[b,d] = dec@Wd^T + topic@Wt^T ; f2 likewise with Wd2/Wt2
// 8192 threads, one per (b,d).
// ---------------------------------------------------------------------------
__global__ void prep_kernel(const float* __restrict__ dec,
                            const float* __restrict__ topic,
                            const float* __restrict__ Wd,
                            const float* __restrict__ Wt,
                            const float* __restrict__ Wd2,
                            const float* __restrict__ Wt2) {
    int idx = blockIdx.x * blockDim.x + threadIdx.x;   // 0..8191
    int b = idx >> 9;
    int d = idx & 511;

    const float* db  = dec + b * DEC;
    const float* wd  = Wd  + (size_t)d * DEC;
    const float* wd2 = Wd2 + (size_t)d * DEC;

    float f1 = 0.f, f2 = 0.f;
    for (int m = 0; m < DEC; m += 4) {
        float4 dv = *(const float4*)(db + m);
        float4 w1 = *(const float4*)(wd + m);
        float4 w2 = *(const float4*)(wd2 + m);
        f1 += dv.x * w1.x + dv.y * w1.y + dv.z * w1.z + dv.w * w1.w;
        f2 += dv.x * w2.x + dv.y * w2.y + dv.z * w2.z + dv.w * w2.w;
    }
    const float* tb  = topic + b * TOPN;
    const float* wt  = Wt  + (size_t)d * TOPN;
    const float* wt2 = Wt2 + (size_t)d * TOPN;
    for (int t = 0; t < TOPN; ++t) {
        float tv = tb[t];
        f1 += tv * wt[t];
        f2 += tv * wt2[t];
    }
    g_f1[idx] = f1;
    g_f2[idx] = f2;
}

// ---------------------------------------------------------------------------
// Kernel B: word-level fused GEMM + tanh + Wv-reduce + softmax.
// One block per (b,q). M=128 words, N=512 d (4 tiles of 128), K=512 m (tiles of 32).
// 256 threads, 8x8 microtile (tx: d-group 0..15, ty: w-group 0..15).
// Writes word_attn into the rescaled output region (scaled later).
// ---------------------------------------------------------------------------
__global__ __launch_bounds__(256, 2) void word_attn_kernel(
    const float* __restrict__ wmem,   // [B,L1,L2,MEM]
    const float* __restrict__ Wm,     // [DEC,MEM]
    const float* __restrict__ Wv,     // [DEC]
    const int*   __restrict__ wmask,  // [B,L1,L2]
    float* __restrict__ attn_out) {   // [B,L1,L2]

    __shared__ float As[32 * 129];          // A tile: [kk][w], stride 129 (conflict-free)
    __shared__ float Bs[32 * 145];          // W tile: [kk][16 groups][9], conflict-free
    __shared__ float sF[DEC];
    __shared__ float sV[DEC];
    __shared__ float sScore[L2];
    __shared__ float sRed[8];

    const int tid = threadIdx.x;
    const int bq  = blockIdx.x;             // b*32 + q
    const int b   = bq >> 5;
    const int tx  = tid & 15;
    const int ty  = tid >> 4;

    const float* Ag = wmem + (size_t)bq * L2 * MEMD;

    for (int i = tid; i < DEC; i += 256) {
        sF[i] = g_f1[b * DEC + i];
        sV[i] = Wv[i];
    }

    float spart[8];
#pragma unroll
    for (int i = 0; i < 8; ++i) spart[i] = 0.f;

    for (int nt = 0; nt < 4; ++nt) {
        const int d0 = nt * 128;
        float acc[8][8];
#pragma unroll
        for (int i = 0; i < 8; ++i)
#pragma unroll
            for (int j = 0; j < 8; ++j) acc[i][j] = 0.f;

        for (int kt = 0; kt < MEMD; kt += 32) {
            __syncthreads();
            const int kk = tid & 31;
            const int rb = tid >> 5;
#pragma unroll
            for (int p = 0; p < 16; ++p) {
                int r = rb + p * 8;                    // 0..127
                As[kk * 129 + r] = Ag[(size_t)r * MEMD + kt + kk];
                Bs[kk * 145 + (r >> 3) * 9 + (r & 7)] =
                    Wm[(size_t)(d0 + r) * MEMD + kt + kk];
            }
            __syncthreads();
#pragma unroll
            for (int k2 = 0; k2 < 32; ++k2) {
                float a[8], bb[8];
#pragma unroll
                for (int i = 0; i < 8; ++i) a[i]  = As[k2 * 129 + ty * 8 + i];
#pragma unroll
                for (int j = 0; j < 8; ++j) bb[j] = Bs[k2 * 145 + tx * 9 + j];
#pragma unroll
                for (int i = 0; i < 8; ++i)
#pragma unroll
                    for (int j = 0; j < 8; ++j)
                        acc[i][j] += a[i] * bb[j];
            }
        }
        // epilogue: tanh + Wv partial reduction (d stays per-thread)
#pragma unroll
        for (int j = 0; j < 8; ++j) {
            int d = d0 + tx * 8 + j;
            float fv = sF[d];
            float wv = sV[d];
#pragma unroll
            for (int i = 0; i < 8; ++i)
                spart[i] += tanhf(acc[i][j] + fv) * wv;
        }
    }

    // reduce over the 16 tx lanes (tx lives in lane bits 0..3)
#pragma unroll
    for (int ofs = 8; ofs; ofs >>= 1)
#pragma unroll
        for (int i = 0; i < 8; ++i)
            spart[i] += __shfl_xor_sync(0xffffffffu, spart[i], ofs);

    if (tx == 0) {
#pragma unroll
        for (int i = 0; i < 8; ++i) sScore[ty * 8 + i] = spart[i];
    }
    __syncthreads();

    // masked softmax over 128 words
    float s = -INFINITY;
    if (tid < L2) {
        s = sScore[tid];
        if (wmask[bq * L2 + tid] == 0) s = -INFINITY;
    }
    float m = s;
#pragma unroll
    for (int ofs = 16; ofs; ofs >>= 1)
        m = fmaxf(m, __shfl_xor_sync(0xffffffffu, m, ofs));
    if ((tid & 31) == 0) sRed[tid >> 5] = m;
    __syncthreads();
    float bmax = sRed[0];
#pragma unroll
    for (int i = 1; i < 8; ++i) bmax = fmaxf(bmax, sRed[i]);

    float e = 0.f;
    if (tid < L2 && bmax > -INFINITY) e = expf(s - bmax);
    __syncthreads();
    float t = e;
#pragma unroll
    for (int ofs = 16; ofs; ofs >>= 1)
        t += __shfl_xor_sync(0xffffffffu, t, ofs);
    if ((tid & 31) == 0) sRed[tid >> 5] = t;
    __syncthreads();
    float bsum = 0.f;
#pragma unroll
    for (int i = 0; i < 8; ++i) bsum += sRed[i];

    if (tid < L2) {
        float a = (bsum > 0.f) ? e / bsum : 0.f;
        attn_out[bq * L2 + tid] = a;
    }
}

// ---------------------------------------------------------------------------
// Kernel C: doc-level scores. One block per (b,q); thread owns d and d+256.
// ---------------------------------------------------------------------------
__global__ void doc_score_kernel(const float* __restrict__ dmem,  // [B,L1,MEM]
                                 const float* __restrict__ Wm2,   // [DEC,MEM]
                                 const float* __restrict__ Wv2) { // [DEC]
    __shared__ __align__(16) float sdoc[MEMD];
    __shared__ float sRed[8];
    const int tid = threadIdx.x;
    const int bq  = blockIdx.x;
    const int b   = bq >> 5;

    const float* drow = dmem + (size_t)bq * MEMD;
    for (int i = tid; i < MEMD; i += 256) sdoc[i] = drow[i];
    __syncthreads();

    const int d0 = tid, d1 = tid + 256;
    const float* w0 = Wm2 + (size_t)d0 * MEMD;
    const float* w1 = Wm2 + (size_t)d1 * MEMD;
    float a0 = 0.f, a1 = 0.f;
    for (int m = 0; m < MEMD; m += 4) {
        float4 dv = *(const float4*)(sdoc + m);
        float4 x0 = *(const float4*)(w0 + m);
        float4 x1 = *(const float4*)(w1 + m);
        a0 += dv.x * x0.x + dv.y * x0.y + dv.z * x0.z + dv.w * x0.w;
        a1 += dv.x * x1.x + dv.y * x1.y + dv.z * x1.z + dv.w * x1.w;
    }
    float v = tanhf(a0 + g_f2[b * DEC + d0]) * Wv2[d0] +
              tanhf(a1 + g_f2[b * DEC + d1]) * Wv2[d1];
#pragma unroll
    for (int ofs = 16; ofs; ofs >>= 1)
        v += __shfl_xor_sync(0xffffffffu, v, ofs);
    if ((tid & 31) == 0) sRed[tid >> 5] = v;
    __syncthreads();
    if (tid == 0) {
        float ssum = 0.f;
#pragma unroll
        for (int i = 0; i < 8; ++i) ssum += sRed[i];
        g_doc_score[bq] = ssum;
    }
}

// ---------------------------------------------------------------------------
// Kernel D: doc softmax (one warp per b) + zero the context output region.
// ---------------------------------------------------------------------------
__global__ void doc_softmax_kernel(const int* __restrict__ dmask,
                                   float* __restrict__ ctx) {
    const int tid = threadIdx.x;   // 0..511
#pragma unroll
    for (int i = 0; i < 16; ++i) ctx[tid + i * 512] = 0.f;   // zero 8192 floats

    float s = g_doc_score[tid];
    if (dmask[tid] == 0) s = -INFINITY;
    float m = s;
#pragma unroll
    for (int ofs = 16; ofs; ofs >>= 1)
        m = fmaxf(m, __shfl_xor_sync(0xffffffffu, m, ofs));
    float e = (m > -INFINITY) ? expf(s - m) : 0.f;
    float sum = e;
#pragma unroll
    for (int ofs = 16; ofs; ofs >>= 1)
        sum += __shfl_xor_sync(0xffffffffu, sum, ofs);
    g_doc_attn[tid] = (sum > 0.f) ? e / sum : 0.f;
}

// ---------------------------------------------------------------------------
// Kernel E: rescaled = doc_attn * word_attn (in place in output), and
// context[b,m] += sum_{q,w} rescaled * word_memory. One block per (b,q).
// ---------------------------------------------------------------------------
__global__ void context_kernel(const float* __restrict__ wmem,
                               float* __restrict__ resc,
                               float* __restrict__ ctx) {
    __shared__ float sr[L2];
    const int tid = threadIdx.x;
    const int bq  = blockIdx.x;
    const int b   = bq >> 5;

    const float da = g_doc_attn[bq];
    if (tid < L2) {
        float r = resc[bq * L2 + tid] * da;
        resc[bq * L2 + tid] = r;
        sr[tid] = r;
    }
    __syncthreads();

    const float* wm = wmem + (size_t)bq * L2 * MEMD;
    const int m0 = tid, m1 = tid + 256;
    float a0 = 0.f, a1 = 0.f;
    for (int w = 0; w < L2; ++w) {
        float r = sr[w];
        a0 += r * wm[(size_t)w * MEMD + m0];
        a1 += r * wm[(size_t)w * MEMD + m1];
    }
    atomicAdd(&ctx[b * MEMD + m0], a0);
    atomicAdd(&ctx[b * MEMD + m1], a1);
}

// ---------------------------------------------------------------------------
extern "C" void kernel_launch(void* const* d_in, const int* in_sizes, int n_in,
                              void* d_out, int out_size) {
    const float* decoder = (const float*)d_in[0];
    const float* dmem    = (const float*)d_in[1];
    const float* wmem    = (const float*)d_in[2];
    const float* topic   = (const float*)d_in[3];
    const int*   dmask   = (const int*)d_in[4];
    const int*   wmask   = (const int*)d_in[5];
    const float* Wv      = (const float*)d_in[6];
    const float* Wd      = (const float*)d_in[7];
    const float* Wt      = (const float*)d_in[8];
    const float* Wm      = (const float*)d_in[9];
    const float* Wv2     = (const float*)d_in[10];
    const float* Wd2     = (const float*)d_in[11];
    const float* Wt2     = (const float*)d_in[12];
    const float* Wm2     = (const float*)d_in[13];

    float* out  = (float*)d_out;
    float* ctx  = out;                  // context [16,512]
    float* resc = out + BB * MEMD;      // rescaled [16,32,128]

    prep_kernel<<<32, 256>>>(decoder, topic, Wd, Wt, Wd2, Wt2);
    word_attn_kernel<<<BB * L1, 256>>>(wmem, Wm, Wv, wmask, resc);
    doc_score_kernel<<<BB * L1, 256>>>(dmem, Wm2, Wv2);
    doc_softmax_kernel<<<1, 512>>>(dmask, ctx);
    context_kernel<<<BB * L1, 256>>>(wmem, resc, ctx);
}

// round 3
// speedup vs baseline: 2.4700x; 2.4700x over previous
#include <cuda_runtime.h>
#include <math.h>
#include <stdint.h>

#define BB 16
#define L1 32
#define L2 128
#define DEC 512
#define MEMD 512
#define TOPN 50

// Scratch (allocation-free rule: __device__ globals)
__device__ float    g_f1[BB * DEC];
__device__ float    g_f2[BB * DEC];
__device__ float    g_doc_score[BB * L1];
__device__ float    g_doc_attn[BB * L1];
__device__ uint32_t g_Wm32[DEC * MEMD];   // Wm pre-converted to tf32 bit patterns

// ============================ helpers =====================================
__device__ __forceinline__ uint32_t smem_u32(const void* p) {
    uint32_t a;
    asm("{ .reg .u64 t; cvta.to.shared.u64 t, %1; cvt.u32.u64 %0, t; }"
        : "=r"(a) : "l"(p));
    return a;
}
__device__ __forceinline__ uint32_t f2tf32(float x) {
    uint32_t u;
    asm("cvt.rna.tf32.f32 %0, %1;" : "=r"(u) : "f"(x));
    return u;
}
#define CP_ASYNC16(dst_u32, src_ptr) \
    asm volatile("cp.async.cg.shared.global [%0], [%1], 16;" \
                 :: "r"(dst_u32), "l"(src_ptr) : "memory")
#define CP_COMMIT() asm volatile("cp.async.commit_group;" ::: "memory")
#define CP_WAIT0()  asm volatile("cp.async.wait_group 0;" ::: "memory")

__device__ __forceinline__ void mma_tf32(float* c, const uint32_t* a, const uint32_t* b) {
    asm volatile(
        "mma.sync.aligned.m16n8k8.row.col.f32.tf32.tf32.f32 "
        "{%0,%1,%2,%3}, {%4,%5,%6,%7}, {%8,%9}, {%0,%1,%2,%3};"
        : "+f"(c[0]), "+f"(c[1]), "+f"(c[2]), "+f"(c[3])
        : "r"(a[0]), "r"(a[1]), "r"(a[2]), "r"(a[3]), "r"(b[0]), "r"(b[1]));
}

// =================== FMA-only tanh (no MUFU) =============================
// abs error ~3e-7; exact 0 at x=0.
__device__ __forceinline__ float tanh_fma(float x) {
    float a = fminf(fabsf(x), 9.0f);
    float y = a * (-2.8853900817779268f);           // -2*log2(e)*a
    float r = y + 12582912.0f;                      // RN-to-int (1.5*2^23)
    int   i = __float_as_int(r) - __float_as_int(12582912.0f);
    float f = y - (r - 12582912.0f);                // frac in [-0.5, 0.5]
    float p = 1.5403530393381606e-4f;
    p = fmaf(p, f, 1.3333558146428443e-3f);
    p = fmaf(p, f, 9.6181291076284770e-3f);
    p = fmaf(p, f, 5.5504108664821600e-2f);
    p = fmaf(p, f, 2.4022650695910072e-1f);
    p = fmaf(p, f, 6.9314718055994531e-1f);
    p = fmaf(p, f, 1.0f);
    float t = __int_as_float(__float_as_int(p) + (i << 23));  // e^{-2a}
    float d = 1.0f + t;
    float rc = __int_as_float(0x7EF311C3 - __float_as_int(d));
    rc = rc * fmaf(-d, rc, 2.0f);
    rc = rc * fmaf(-d, rc, 2.0f);
    rc = rc * fmaf(-d, rc, 2.0f);
    float th = (1.0f - t) * rc;
    return __int_as_float(__float_as_int(th) | (__float_as_int(x) & 0x80000000));
}

// ---------------------------------------------------------------------------
// Kernel A: f1/f2 bias vectors, zero doc scores, convert Wm -> tf32.
// ---------------------------------------------------------------------------
__global__ void prep_kernel(const float* __restrict__ dec,
                            const float* __restrict__ topic,
                            const float* __restrict__ Wd,
                            const float* __restrict__ Wt,
                            const float* __restrict__ Wd2,
                            const float* __restrict__ Wt2,
                            const float* __restrict__ Wm) {
    int idx = blockIdx.x * blockDim.x + threadIdx.x;   // 0..8191
    int b = idx >> 9;
    int d = idx & 511;
    if (idx < BB * L1) g_doc_score[idx] = 0.f;

    // Wm -> tf32 (262144 elems / 8192 threads = 32 each)
    for (int i = idx; i < DEC * MEMD; i += 8192) g_Wm32[i] = f2tf32(Wm[i]);

    const float* db  = dec + b * DEC;
    const float* wd  = Wd  + (size_t)d * DEC;
    const float* wd2 = Wd2 + (size_t)d * DEC;

    float f1 = 0.f, f2 = 0.f;
    for (int m = 0; m < DEC; m += 4) {
        float4 dv = *(const float4*)(db + m);
        float4 w1 = *(const float4*)(wd + m);
        float4 w2 = *(const float4*)(wd2 + m);
        f1 += dv.x * w1.x + dv.y * w1.y + dv.z * w1.z + dv.w * w1.w;
        f2 += dv.x * w2.x + dv.y * w2.y + dv.z * w2.z + dv.w * w2.w;
    }
    const float* tb  = topic + b * TOPN;
    const float* wt  = Wt  + (size_t)d * TOPN;
    const float* wt2 = Wt2 + (size_t)d * TOPN;
    for (int t = 0; t < TOPN; ++t) {
        float tv = tb[t];
        f1 += tv * wt[t];
        f2 += tv * wt2[t];
    }
    g_f1[idx] = f1;
    g_f2[idx] = f2;
}

// ---------------------------------------------------------------------------
// Kernel B: word-level fused tf32 mma.sync GEMM + tanh + Wv-reduce + softmax.
// One (b,q) per CTA. M=128 (w), K=512 (m), N=512 d in 2 chunks of 256.
// 8 warps = 2(m) x 4(n); warp tile 64x64; mma m16n8k8.
// SMEM float layout (stride-36 padded rows, conflict-free frag loads):
//   As[2][128*36] | Bs[2][256*36] | sF[512] | sV[512] | sSc[128] | sRd[8]
// ---------------------------------------------------------------------------
#define ASTRIDE 36
#define AS_F    (128 * ASTRIDE)           // 4608 floats per buffer
#define BS_F    (256 * ASTRIDE)           // 9216 floats per buffer
#define OFF_B   (2 * AS_F)                // 9216
#define OFF_F   (OFF_B + 2 * BS_F)        // 27648
#define OFF_V   (OFF_F + 512)
#define OFF_SC  (OFF_V + 512)
#define OFF_RD  (OFF_SC + 128)
#define SMEM_FLOATS (OFF_RD + 8)
#define SMEM_BYTES  (SMEM_FLOATS * 4)

__global__ __launch_bounds__(256, 1)
void word_attn_tc(const float* __restrict__ wmem,   // [B,L1,L2,MEM]
                  const float* __restrict__ Wv,     // [DEC]
                  const int*   __restrict__ wmask,  // [B,L1,L2]
                  float* __restrict__ attn_out) {   // [B,L1,L2]
    extern __shared__ float smf[];
    float* As0 = smf;
    float* Bs0 = smf + OFF_B;
    float* sF  = smf + OFF_F;
    float* sV  = smf + OFF_V;
    float* sSc = smf + OFF_SC;
    float* sRd = smf + OFF_RD;

    const int tid    = threadIdx.x;
    const int wid    = tid >> 5;
    const int lane   = tid & 31;
    const int g      = lane >> 2;      // groupID
    const int tg     = lane & 3;       // threadID_in_group
    const int warp_m = wid >> 2;       // 0..1
    const int warp_n = wid & 3;        // 0..3
    const int bq     = blockIdx.x;
    const int b      = bq >> 5;

    for (int i = tid; i < DEC; i += 256) {
        sF[i] = g_f1[b * DEC + i];
        sV[i] = Wv[i];
    }
    if (tid < L2) sSc[tid] = 0.f;
    __syncthreads();

    const float4* A4 = (const float4*)(wmem + (size_t)bq * L2 * MEMD);

    // per-thread row sums: rows warp_m*64 + mt*16 + g (+8)
    float rs[4][2];
#pragma unroll
    for (int mt = 0; mt < 4; ++mt) { rs[mt][0] = 0.f; rs[mt][1] = 0.f; }

    const uint32_t bs_u32 = smem_u32(Bs0);

    for (int ntc = 0; ntc < 2; ++ntc) {
        float acc[4][8][4];
#pragma unroll
        for (int mt = 0; mt < 4; ++mt)
#pragma unroll
            for (int nt = 0; nt < 8; ++nt)
#pragma unroll
                for (int i = 0; i < 4; ++i) acc[mt][nt][i] = 0.f;

        // ---- prologue: chunk 0 into buffer 0 ----
        {
#pragma unroll
            for (int i = 0; i < 8; ++i) {        // B via cp.async (tf32 ready)
                int idx = tid + 256 * i, row = idx >> 3, c4 = idx & 7;
                const uint32_t* gp = g_Wm32 + (size_t)(ntc * 256 + row) * MEMD + c4 * 4;
                CP_ASYNC16(bs_u32 + (row * ASTRIDE + c4 * 4) * 4, gp);
            }
            CP_COMMIT();
#pragma unroll
            for (int i = 0; i < 4; ++i) {        // A: LDG -> cvt -> STS
                int idx = tid + 256 * i, row = idx >> 3, c4 = idx & 7;
                float4 v = A4[row * 128 + c4];
                uint4 u = {f2tf32(v.x), f2tf32(v.y), f2tf32(v.z), f2tf32(v.w)};
                *(uint4*)(As0 + row * ASTRIDE + c4 * 4) = u;
            }
            CP_WAIT0();
        }
        __syncthreads();

        for (int kc = 0; kc < 16; ++kc) {
            const int cur = kc & 1, nxt = 1 - cur;
            const float* As = As0 + cur * AS_F;
            const float* Bs = Bs0 + cur * BS_F;

            float4 ar[4];
            if (kc < 15) {
#pragma unroll
                for (int i = 0; i < 8; ++i) {
                    int idx = tid + 256 * i, row = idx >> 3, c4 = idx & 7;
                    const uint32_t* gp = g_Wm32 +
                        (size_t)(ntc * 256 + row) * MEMD + (kc + 1) * 32 + c4 * 4;
                    CP_ASYNC16(bs_u32 + (nxt * BS_F + row * ASTRIDE + c4 * 4) * 4, gp);
                }
                CP_COMMIT();
#pragma unroll
                for (int i = 0; i < 4; ++i) {
                    int idx = tid + 256 * i, row = idx >> 3, c4 = idx & 7;
                    ar[i] = A4[row * 128 + (kc + 1) * 8 + c4];
                }
            }

            // ---- 4 k-steps of mma ----
#pragma unroll
            for (int ks = 0; ks < 4; ++ks) {
                const int kb = ks * 8;
                uint32_t afr[4][4], bfr[8][2];
#pragma unroll
                for (int mt = 0; mt < 4; ++mt) {
                    const float* ap = As + (warp_m * 64 + mt * 16 + g) * ASTRIDE + kb + tg;
                    afr[mt][0] = __float_as_uint(ap[0]);
                    afr[mt][1] = __float_as_uint(ap[8 * ASTRIDE]);
                    afr[mt][2] = __float_as_uint(ap[4]);
                    afr[mt][3] = __float_as_uint(ap[8 * ASTRIDE + 4]);
                }
#pragma unroll
                for (int nt = 0; nt < 8; ++nt) {
                    const float* bp = Bs + (warp_n * 64 + nt * 8 + g) * ASTRIDE + kb + tg;
                    bfr[nt][0] = __float_as_uint(bp[0]);
                    bfr[nt][1] = __float_as_uint(bp[4]);
                }
#pragma unroll
                for (int mt = 0; mt < 4; ++mt)
#pragma unroll
                    for (int nt = 0; nt < 8; ++nt)
                        mma_tf32(acc[mt][nt], afr[mt], bfr[nt]);
            }

            if (kc < 15) {
                float* Asn = As0 + nxt * AS_F;
#pragma unroll
                for (int i = 0; i < 4; ++i) {
                    int idx = tid + 256 * i, row = idx >> 3, c4 = idx & 7;
                    uint4 u = {f2tf32(ar[i].x), f2tf32(ar[i].y),
                               f2tf32(ar[i].z), f2tf32(ar[i].w)};
                    *(uint4*)(Asn + row * ASTRIDE + c4 * 4) = u;
                }
                CP_WAIT0();
            }
            __syncthreads();
        }

        // ---- epilogue: tanh + Wv dot into per-row partials ----
#pragma unroll
        for (int mt = 0; mt < 4; ++mt) {
#pragma unroll
            for (int nt = 0; nt < 8; ++nt) {
                const int d0 = ntc * 256 + warp_n * 64 + nt * 8 + 2 * tg;
                float w0 = sV[d0], w1 = sV[d0 + 1];
                float f0 = sF[d0], f1v = sF[d0 + 1];
                rs[mt][0] += tanh_fma(acc[mt][nt][0] + f0) * w0 +
                             tanh_fma(acc[mt][nt][1] + f1v) * w1;
                rs[mt][1] += tanh_fma(acc[mt][nt][2] + f0) * w0 +
                             tanh_fma(acc[mt][nt][3] + f1v) * w1;
            }
        }
    }

    // reduce across the 4 lanes of each group (tg bits)
#pragma unroll
    for (int ofs = 1; ofs <= 2; ofs <<= 1)
#pragma unroll
        for (int mt = 0; mt < 4; ++mt) {
            rs[mt][0] += __shfl_xor_sync(0xffffffffu, rs[mt][0], ofs);
            rs[mt][1] += __shfl_xor_sync(0xffffffffu, rs[mt][1], ofs);
        }
    if (tg == 0) {
#pragma unroll
        for (int mt = 0; mt < 4; ++mt) {
            atomicAdd(&sSc[warp_m * 64 + mt * 16 + g],     rs[mt][0]);
            atomicAdd(&sSc[warp_m * 64 + mt * 16 + 8 + g], rs[mt][1]);
        }
    }
    __syncthreads();

    // masked softmax over 128 words
    float s = -INFINITY;
    if (tid < L2) {
        s = sSc[tid];
        if (wmask[bq * L2 + tid] == 0) s = -INFINITY;
    }
    float m = s;
#pragma unroll
    for (int ofs = 16; ofs; ofs >>= 1)
        m = fmaxf(m, __shfl_xor_sync(0xffffffffu, m, ofs));
    if (lane == 0) sRd[wid] = m;
    __syncthreads();
    float bmax = sRd[0];
#pragma unroll
    for (int i = 1; i < 8; ++i) bmax = fmaxf(bmax, sRd[i]);

    float e = 0.f;
    if (tid < L2 && bmax > -INFINITY) e = expf(s - bmax);
    __syncthreads();
    float t = e;
#pragma unroll
    for (int ofs = 16; ofs; ofs >>= 1)
        t += __shfl_xor_sync(0xffffffffu, t, ofs);
    if (lane == 0) sRd[wid] = t;
    __syncthreads();
    float bsum = 0.f;
#pragma unroll
    for (int i = 0; i < 8; ++i) bsum += sRd[i];

    if (tid < L2)
        attn_out[bq * L2 + tid] = (bsum > 0.f) ? e / bsum : 0.f;
}

// ---------------------------------------------------------------------------
// Kernel C: doc-level partial scores. Grid = 16 b x 8 d-chunks; atomicAdd.
// ---------------------------------------------------------------------------
__global__ void doc_score_kernel(const float* __restrict__ dmem,  // [B,L1,MEM]
                                 const float* __restrict__ Wm2,   // [DEC,MEM]
                                 const float* __restrict__ Wv2) { // [DEC]
    extern __shared__ float sdoc[];   // 32*512
    const int tid = threadIdx.x;
    const int b   = blockIdx.x >> 3;
    const int dc  = blockIdx.x & 7;

    const float* drow = dmem + (size_t)b * L1 * MEMD;
    for (int i = tid; i < L1 * MEMD; i += 256) sdoc[i] = drow[i];
    __syncthreads();

    const int q    = tid >> 3;
    const int dsub = tid & 7;
    float acc = 0.f;
    for (int k = 0; k < 8; ++k) {
        const int d = dc * 64 + dsub * 8 + k;
        const float4* w = (const float4*)(Wm2 + (size_t)d * MEMD);
        const float4* x = (const float4*)(sdoc + q * MEMD);
        float s0 = 0.f;
#pragma unroll 8
        for (int mm = 0; mm < 128; ++mm) {
            float4 wv = w[mm], xv = x[mm];
            s0 += wv.x * xv.x + wv.y * xv.y + wv.z * xv.z + wv.w * xv.w;
        }
        acc += tanh_fma(s0 + g_f2[b * DEC + d]) * Wv2[d];
    }
    atomicAdd(&g_doc_score[b * L1 + q], acc);
}

// ---------------------------------------------------------------------------
// Kernel D: doc softmax (one warp per b) + zero the context output region.
// ---------------------------------------------------------------------------
__global__ void doc_softmax_kernel(const int* __restrict__ dmask,
                                   float* __restrict__ ctx) {
    const int tid = threadIdx.x;   // 0..511
#pragma unroll
    for (int i = 0; i < 16; ++i) ctx[tid + i * 512] = 0.f;

    float s = g_doc_score[tid];
    if (dmask[tid] == 0) s = -INFINITY;
    float m = s;
#pragma unroll
    for (int ofs = 16; ofs; ofs >>= 1)
        m = fmaxf(m, __shfl_xor_sync(0xffffffffu, m, ofs));
    float e = (m > -INFINITY) ? expf(s - m) : 0.f;
    float sum = e;
#pragma unroll
    for (int ofs = 16; ofs; ofs >>= 1)
        sum += __shfl_xor_sync(0xffffffffu, sum, ofs);
    g_doc_attn[tid] = (sum > 0.f) ? e / sum : 0.f;
}

// ---------------------------------------------------------------------------
// Kernel E: rescaled = doc_attn * word_attn (in place), context accumulate.
// ---------------------------------------------------------------------------
__global__ void context_kernel(const float* __restrict__ wmem,
                               float* __restrict__ resc,
                               float* __restrict__ ctx) {
    __shared__ float sr[L2];
    const int tid = threadIdx.x;
    const int bq  = blockIdx.x;
    const int b   = bq >> 5;

    const float da = g_doc_attn[bq];
    if (tid < L2) {
        float r = resc[bq * L2 + tid] * da;
        resc[bq * L2 + tid] = r;
        sr[tid] = r;
    }
    __syncthreads();

    const float* wm = wmem + (size_t)bq * L2 * MEMD;
    const int m0 = tid, m1 = tid + 256;
    float a0 = 0.f, a1 = 0.f;
    for (int w = 0; w < L2; ++w) {
        float r = sr[w];
        a0 += r * wm[(size_t)w * MEMD + m0];
        a1 += r * wm[(size_t)w * MEMD + m1];
    }
    atomicAdd(&ctx[b * MEMD + m0], a0);
    atomicAdd(&ctx[b * MEMD + m1], a1);
}

// ---------------------------------------------------------------------------
extern "C" void kernel_launch(void* const* d_in, const int* in_sizes, int n_in,
                              void* d_out, int out_size) {
    const float* decoder = (const float*)d_in[0];
    const float* dmem    = (const float*)d_in[1];
    const float* wmem    = (const float*)d_in[2];
    const float* topic   = (const float*)d_in[3];
    const int*   dmask   = (const int*)d_in[4];
    const int*   wmask   = (const int*)d_in[5];
    const float* Wv      = (const float*)d_in[6];
    const float* Wd      = (const float*)d_in[7];
    const float* Wt      = (const float*)d_in[8];
    const float* Wm      = (const float*)d_in[9];
    const float* Wv2     = (const float*)d_in[10];
    const float* Wd2     = (const float*)d_in[11];
    const float* Wt2     = (const float*)d_in[12];
    const float* Wm2     = (const float*)d_in[13];

    float* out  = (float*)d_out;
    float* ctx  = out;                  // context [16,512]
    float* resc = out + BB * MEMD;      // rescaled [16,32,128]

    cudaFuncSetAttribute(word_attn_tc,
                         cudaFuncAttributeMaxDynamicSharedMemorySize, SMEM_BYTES);
    cudaFuncSetAttribute(doc_score_kernel,
                         cudaFuncAttributeMaxDynamicSharedMemorySize, 65536);

    prep_kernel<<<32, 256>>>(decoder, topic, Wd, Wt, Wd2, Wt2, Wm);
    word_attn_tc<<<BB * L1, 256, SMEM_BYTES>>>(wmem, Wv, wmask, resc);
    doc_score_kernel<<<BB * 8, 256, 65536>>>(dmem, Wm2, Wv2);
    doc_softmax_kernel<<<1, 512>>>(dmask, ctx);
    context_kernel<<<BB * L1, 256>>>(wmem, resc, ctx);
}

// round 4
// speedup vs baseline: 3.0616x; 1.2395x over previous
#include <cuda_runtime.h>
#include <cuda_fp16.h>
#include <math.h>
#include <stdint.h>

#define BB 16
#define L1 32
#define L2 128
#define DEC 512
#define MEMD 512
#define TOPN 50

// Scratch (allocation-free rule: __device__ globals)
__device__ float    g_f1[BB * DEC];
__device__ float    g_f2[BB * DEC];
__device__ float    g_doc_score[BB * L1];
__device__ float    g_doc_attn[BB * L1];
__device__ uint32_t g_Wmh[DEC * MEMD / 2];   // Wm as half2 pairs
__device__ float    g_ctxp[BB * L1 * MEMD];  // per-(b,q) partial context

// ============================ helpers =====================================
__device__ __forceinline__ uint32_t smem_u32(const void* p) {
    uint32_t a;
    asm("{ .reg .u64 t; cvta.to.shared.u64 t, %1; cvt.u32.u64 %0, t; }"
        : "=r"(a) : "l"(p));
    return a;
}
#define CP_ASYNC16(dst_u32, src_ptr) \
    asm volatile("cp.async.cg.shared.global [%0], [%1], 16;" \
                 :: "r"(dst_u32), "l"(src_ptr) : "memory")
#define CP_COMMIT() asm volatile("cp.async.commit_group;" ::: "memory")
#define CP_WAIT0()  asm volatile("cp.async.wait_group 0;" ::: "memory")

__device__ __forceinline__ float tanh_hw(float x) {
    float y;
    asm("tanh.approx.f32 %0, %1;" : "=f"(y) : "f"(x));
    return y;
}

__device__ __forceinline__ void mma_f16(float* c, const uint32_t* a, const uint32_t* b) {
    asm volatile(
        "mma.sync.aligned.m16n8k16.row.col.f32.f16.f16.f32 "
        "{%0,%1,%2,%3}, {%4,%5,%6,%7}, {%8,%9}, {%0,%1,%2,%3};"
        : "+f"(c[0]), "+f"(c[1]), "+f"(c[2]), "+f"(c[3])
        : "r"(a[0]), "r"(a[1]), "r"(a[2]), "r"(a[3]), "r"(b[0]), "r"(b[1]));
}

__device__ __forceinline__ uint32_t pack_h2(float x, float y) {
    __half2 h = __floats2half2_rn(x, y);
    return *(uint32_t*)&h;
}

// ---------------------------------------------------------------------------
// Kernel A: f1/f2 bias vectors, zero doc scores, convert Wm -> fp16 pairs.
// ---------------------------------------------------------------------------
__global__ void prep_kernel(const float* __restrict__ dec,
                            const float* __restrict__ topic,
                            const float* __restrict__ Wd,
                            const float* __restrict__ Wt,
                            const float* __restrict__ Wd2,
                            const float* __restrict__ Wt2,
                            const float* __restrict__ Wm) {
    int idx = blockIdx.x * blockDim.x + threadIdx.x;   // 0..8191
    int b = idx >> 9;
    int d = idx & 511;
    if (idx < BB * L1) g_doc_score[idx] = 0.f;

    // Wm -> half2 (131072 words / 8192 threads = 16 each)
    for (int i = idx; i < DEC * MEMD / 2; i += 8192) {
        float2 v = ((const float2*)Wm)[i];
        g_Wmh[i] = pack_h2(v.x, v.y);
    }

    const float* db  = dec + b * DEC;
    const float* wd  = Wd  + (size_t)d * DEC;
    const float* wd2 = Wd2 + (size_t)d * DEC;

    float f1 = 0.f, f2 = 0.f;
    for (int m = 0; m < DEC; m += 4) {
        float4 dv = *(const float4*)(db + m);
        float4 w1 = *(const float4*)(wd + m);
        float4 w2 = *(const float4*)(wd2 + m);
        f1 += dv.x * w1.x + dv.y * w1.y + dv.z * w1.z + dv.w * w1.w;
        f2 += dv.x * w2.x + dv.y * w2.y + dv.z * w2.z + dv.w * w2.w;
    }
    const float* tb  = topic + b * TOPN;
    const float* wt  = Wt  + (size_t)d * TOPN;
    const float* wt2 = Wt2 + (size_t)d * TOPN;
    for (int t = 0; t < TOPN; ++t) {
        float tv = tb[t];
        f1 += tv * wt[t];
        f2 += tv * wt2[t];
    }
    g_f1[idx] = f1;
    g_f2[idx] = f2;
}

// ---------------------------------------------------------------------------
// Kernel B: word-level fused fp16 mma.sync GEMM + tanh + Wv-reduce + softmax
//           + partial context from the resident A tile.
// One (b,q) per CTA. M=128(w), K=512(m), N=512 d in 2 chunks of 256.
// 8 warps = 2(m) x 4(n); warp tile 64x64; mma m16n8k16.
// SMEM: A tile fp16 resident 128x512 (row stride 520 halves = 260 words),
//       B double buffers 256x32 halves (row stride 40 halves = 20 words).
// ---------------------------------------------------------------------------
#define AW 260                    // A row stride in 32-bit words
#define BW 20                     // B row stride in 32-bit words
#define BBUF_W (256 * BW)         // 5120 words per B buffer
#define OFF_BBUF 133120           // bytes: after A tile (128*260*4)
#define OFF_F    174080           // after 2 B buffers (2*5120*4)
#define OFF_V    176128
#define OFF_SC   178176
#define OFF_RD   178688
#define SMEM_BYTES 178720

__global__ __launch_bounds__(256, 1)
void word_attn_tc(const float* __restrict__ wmem,   // [B,L1,L2,MEM]
                  const float* __restrict__ Wv,     // [DEC]
                  const int*   __restrict__ wmask,  // [B,L1,L2]
                  float* __restrict__ attn_out) {   // [B,L1,L2]
    extern __shared__ char smem[];
    uint32_t* smA = (uint32_t*)smem;
    uint32_t* smB = (uint32_t*)(smem + OFF_BBUF);
    float* sF  = (float*)(smem + OFF_F);
    float* sV  = (float*)(smem + OFF_V);
    float* sSc = (float*)(smem + OFF_SC);
    float* sRd = (float*)(smem + OFF_RD);

    const int tid    = threadIdx.x;
    const int wid    = tid >> 5;
    const int lane   = tid & 31;
    const int g      = lane >> 2;      // groupID
    const int tg     = lane & 3;       // threadID_in_group
    const int warp_m = wid >> 2;       // 0..1
    const int warp_n = wid & 3;        // 0..3
    const int bq     = blockIdx.x;
    const int b      = bq >> 5;

    const uint32_t smB_u32 = smem_u32(smB);

    // --- prologue: issue B chunk0 (ntc=0) first, then convert A, aux loads ---
    {
#pragma unroll
        for (int i = 0; i < 4; ++i) {
            int idx = tid + 256 * i, row = idx >> 2, q = idx & 3;
            const uint32_t* gp = g_Wmh + (size_t)row * 256 + q * 4;
            CP_ASYNC16(smB_u32 + (row * BW + q * 4) * 4, gp);
        }
        CP_COMMIT();
    }
    {
        const float4* A4 = (const float4*)(wmem + (size_t)bq * L2 * MEMD);
#pragma unroll 4
        for (int i = 0; i < 64; ++i) {
            int idx = tid + 256 * i;          // 16384 float4 total
            int row = idx >> 7, c = idx & 127;
            float4 v = A4[idx];
            uint32_t* dst = smA + row * AW + c * 2;
            dst[0] = pack_h2(v.x, v.y);
            dst[1] = pack_h2(v.z, v.w);
        }
    }
    for (int i = tid; i < DEC; i += 256) {
        sF[i] = g_f1[b * DEC + i];
        sV[i] = Wv[i];
    }
    if (tid < L2) sSc[tid] = 0.f;
    CP_WAIT0();
    __syncthreads();

    for (int ntc = 0; ntc < 2; ++ntc) {
        float acc[4][8][4];
#pragma unroll
        for (int mt = 0; mt < 4; ++mt)
#pragma unroll
            for (int nt = 0; nt < 8; ++nt)
#pragma unroll
                for (int i = 0; i < 4; ++i) acc[mt][nt][i] = 0.f;

        // for ntc=1: issue its chunk0 into buffer 0
        if (ntc == 1) {
#pragma unroll
            for (int i = 0; i < 4; ++i) {
                int idx = tid + 256 * i, row = idx >> 2, q = idx & 3;
                const uint32_t* gp = g_Wmh + (size_t)(256 + row) * 256 + q * 4;
                CP_ASYNC16(smB_u32 + (row * BW + q * 4) * 4, gp);
            }
            CP_COMMIT();
            CP_WAIT0();
            __syncthreads();
        }

        for (int kc = 0; kc < 16; ++kc) {
            const int cur = kc & 1, nxt = 1 - cur;
            if (kc < 15) {
#pragma unroll
                for (int i = 0; i < 4; ++i) {
                    int idx = tid + 256 * i, row = idx >> 2, q = idx & 3;
                    const uint32_t* gp = g_Wmh +
                        (size_t)(ntc * 256 + row) * 256 + (kc + 1) * 16 + q * 4;
                    CP_ASYNC16(smB_u32 + (nxt * BBUF_W + row * BW + q * 4) * 4, gp);
                }
                CP_COMMIT();
            }

            const uint32_t* Bb = smB + cur * BBUF_W;
#pragma unroll
            for (int ks = 0; ks < 2; ++ks) {
                const int akw = kc * 16 + ks * 8 + tg;   // A word offset in row
                uint32_t afr[4][4], bfr[8][2];
#pragma unroll
                for (int mt = 0; mt < 4; ++mt) {
                    const uint32_t* ap = smA + (warp_m * 64 + mt * 16 + g) * AW + akw;
                    afr[mt][0] = ap[0];
                    afr[mt][1] = ap[8 * AW];
                    afr[mt][2] = ap[4];
                    afr[mt][3] = ap[8 * AW + 4];
                }
#pragma unroll
                for (int nt = 0; nt < 8; ++nt) {
                    const uint32_t* bp = Bb + (warp_n * 64 + nt * 8 + g) * BW + ks * 8 + tg;
                    bfr[nt][0] = bp[0];
                    bfr[nt][1] = bp[4];
                }
#pragma unroll
                for (int mt = 0; mt < 4; ++mt)
#pragma unroll
                    for (int nt = 0; nt < 8; ++nt)
                        mma_f16(acc[mt][nt], afr[mt], bfr[nt]);
            }

            if (kc < 15) CP_WAIT0();
            __syncthreads();
        }

        // ---- epilogue: tanh + Wv dot into per-row partials ----
        float rs[4][2];
#pragma unroll
        for (int mt = 0; mt < 4; ++mt) { rs[mt][0] = 0.f; rs[mt][1] = 0.f; }
#pragma unroll
        for (int mt = 0; mt < 4; ++mt) {
#pragma unroll
            for (int nt = 0; nt < 8; ++nt) {
                const int d0 = ntc * 256 + warp_n * 64 + nt * 8 + 2 * tg;
                float w0 = sV[d0], w1 = sV[d0 + 1];
                float f0 = sF[d0], f1v = sF[d0 + 1];
                rs[mt][0] += tanh_hw(acc[mt][nt][0] + f0) * w0 +
                             tanh_hw(acc[mt][nt][1] + f1v) * w1;
                rs[mt][1] += tanh_hw(acc[mt][nt][2] + f0) * w0 +
                             tanh_hw(acc[mt][nt][3] + f1v) * w1;
            }
        }
#pragma unroll
        for (int ofs = 1; ofs <= 2; ofs <<= 1)
#pragma unroll
            for (int mt = 0; mt < 4; ++mt) {
                rs[mt][0] += __shfl_xor_sync(0xffffffffu, rs[mt][0], ofs);
                rs[mt][1] += __shfl_xor_sync(0xffffffffu, rs[mt][1], ofs);
            }
        if (tg == 0) {
#pragma unroll
            for (int mt = 0; mt < 4; ++mt) {
                atomicAdd(&sSc[warp_m * 64 + mt * 16 + g],     rs[mt][0]);
                atomicAdd(&sSc[warp_m * 64 + mt * 16 + 8 + g], rs[mt][1]);
            }
        }
    }
    __syncthreads();

    // ---- masked softmax over 128 words ----
    float s = -INFINITY;
    if (tid < L2) {
        s = sSc[tid];
        if (wmask[bq * L2 + tid] == 0) s = -INFINITY;
    }
    float m = s;
#pragma unroll
    for (int ofs = 16; ofs; ofs >>= 1)
        m = fmaxf(m, __shfl_xor_sync(0xffffffffu, m, ofs));
    if (lane == 0) sRd[wid] = m;
    __syncthreads();
    float bmax = sRd[0];
#pragma unroll
    for (int i = 1; i < 8; ++i) bmax = fmaxf(bmax, sRd[i]);

    float e = 0.f;
    if (tid < L2 && bmax > -INFINITY) e = expf(s - bmax);
    float t = e;
#pragma unroll
    for (int ofs = 16; ofs; ofs >>= 1)
        t += __shfl_xor_sync(0xffffffffu, t, ofs);
    if (lane == 0) sRd[wid] = t;
    __syncthreads();
    float bsum = 0.f;
#pragma unroll
    for (int i = 0; i < 8; ++i) bsum += sRd[i];

    float attn = 0.f;
    if (tid < L2) {
        attn = (bsum > 0.f) ? e / bsum : 0.f;
        attn_out[bq * L2 + tid] = attn;
    }
    __syncthreads();                 // sSc reads done; safe to overwrite
    if (tid < L2) sSc[tid] = attn;
    __syncthreads();

    // ---- partial context from resident A tile: ctxp[m] = sum_w attn[w]*A[w][m]
    float cx = 0.f, cy = 0.f;        // this thread owns m = 2*tid, 2*tid+1
#pragma unroll 8
    for (int w = 0; w < L2; ++w) {
        float a = sSc[w];
        uint32_t hv = smA[w * AW + tid];
        __half2 h = *(__half2*)&hv;
        float2 f = __half22float2(h);
        cx = fmaf(a, f.x, cx);
        cy = fmaf(a, f.y, cy);
    }
    g_ctxp[bq * MEMD + 2 * tid]     = cx;
    g_ctxp[bq * MEMD + 2 * tid + 1] = cy;
}

// ---------------------------------------------------------------------------
// Kernel C: doc-level partial scores. Grid = 16 b x 8 d-chunks; atomicAdd.
// ---------------------------------------------------------------------------
__global__ void doc_score_kernel(const float* __restrict__ dmem,  // [B,L1,MEM]
                                 const float* __restrict__ Wm2,   // [DEC,MEM]
                                 const float* __restrict__ Wv2) { // [DEC]
    extern __shared__ float sdoc[];   // 32*512
    const int tid = threadIdx.x;
    const int b   = blockIdx.x >> 3;
    const int dc  = blockIdx.x & 7;

    const float* drow = dmem + (size_t)b * L1 * MEMD;
    for (int i = tid; i < L1 * MEMD; i += 256) sdoc[i] = drow[i];
    __syncthreads();

    const int q    = tid >> 3;
    const int dsub = tid & 7;
    float acc = 0.f;
    for (int k = 0; k < 8; ++k) {
        const int d = dc * 64 + dsub * 8 + k;
        const float4* w = (const float4*)(Wm2 + (size_t)d * MEMD);
        const float4* x = (const float4*)(sdoc + q * MEMD);
        float s0 = 0.f;
#pragma unroll 8
        for (int mm = 0; mm < 128; ++mm) {
            float4 wv = w[mm], xv = x[mm];
            s0 += wv.x * xv.x + wv.y * xv.y + wv.z * xv.z + wv.w * xv.w;
        }
        acc += tanh_hw(s0 + g_f2[b * DEC + d]) * Wv2[d];
    }
    atomicAdd(&g_doc_score[b * L1 + q], acc);
}

// ---------------------------------------------------------------------------
// Kernel D: doc softmax (one warp per b).
// ---------------------------------------------------------------------------
__global__ void doc_softmax_kernel(const int* __restrict__ dmask) {
    const int tid = threadIdx.x;   // 0..511
    float s = g_doc_score[tid];
    if (dmask[tid] == 0) s = -INFINITY;
    float m = s;
#pragma unroll
    for (int ofs = 16; ofs; ofs >>= 1)
        m = fmaxf(m, __shfl_xor_sync(0xffffffffu, m, ofs));
    float e = (m > -INFINITY) ? expf(s - m) : 0.f;
    float sum = e;
#pragma unroll
    for (int ofs = 16; ofs; ofs >>= 1)
        sum += __shfl_xor_sync(0xffffffffu, sum, ofs);
    g_doc_attn[tid] = (sum > 0.f) ? e / sum : 0.f;
}

// ---------------------------------------------------------------------------
// Kernel E: combine. ctx[b][m] = sum_q doc_attn*ctxp; resc *= doc_attn.
// ---------------------------------------------------------------------------
__global__ void combine_kernel(float* __restrict__ ctx,
                               float* __restrict__ resc) {
    const int b = blockIdx.x;       // 16
    const int tid = threadIdx.x;    // 512
    float acc = 0.f;
#pragma unroll 8
    for (int q = 0; q < L1; ++q)
        acc = fmaf(g_doc_attn[b * L1 + q], g_ctxp[(b * L1 + q) * MEMD + tid], acc);
    ctx[b * MEMD + tid] = acc;

#pragma unroll
    for (int i = 0; i < 8; ++i) {
        int idx = tid + i * 512;    // 0..4095
        resc[b * (L1 * L2) + idx] *= g_doc_attn[b * L1 + (idx >> 7)];
    }
}

// ---------------------------------------------------------------------------
extern "C" void kernel_launch(void* const* d_in, const int* in_sizes, int n_in,
                              void* d_out, int out_size) {
    const float* decoder = (const float*)d_in[0];
    const float* dmem    = (const float*)d_in[1];
    const float* wmem    = (const float*)d_in[2];
    const float* topic   = (const float*)d_in[3];
    const int*   dmask   = (const int*)d_in[4];
    const int*   wmask   = (const int*)d_in[5];
    const float* Wv      = (const float*)d_in[6];
    const float* Wd      = (const float*)d_in[7];
    const float* Wt      = (const float*)d_in[8];
    const float* Wm      = (const float*)d_in[9];
    const float* Wv2     = (const float*)d_in[10];
    const float* Wd2     = (const float*)d_in[11];
    const float* Wt2     = (const float*)d_in[12];
    const float* Wm2     = (const float*)d_in[13];

    float* out  = (float*)d_out;
    float* ctx  = out;                  // context [16,512]
    float* resc = out + BB * MEMD;      // rescaled [16,32,128]

    cudaFuncSetAttribute(word_attn_tc,
                         cudaFuncAttributeMaxDynamicSharedMemorySize, SMEM_BYTES);
    cudaFuncSetAttribute(doc_score_kernel,
                         cudaFuncAttributeMaxDynamicSharedMemorySize, 65536);

    prep_kernel<<<32, 256>>>(decoder, topic, Wd, Wt, Wd2, Wt2, Wm);
    word_attn_tc<<<BB * L1, 256, SMEM_BYTES>>>(wmem, Wv, wmask, resc);
    doc_score_kernel<<<BB * 8, 256, 65536>>>(dmem, Wm2, Wv2);
    doc_softmax_kernel<<<1, 512>>>(dmask);
    combine_kernel<<<BB, 512>>>(ctx, resc);
}

// round 5
// speedup vs baseline: 3.0989x; 1.0122x over previous
#include <cuda_runtime.h>
#include <cuda_fp16.h>
#include <math.h>
#include <stdint.h>

#define BB 16
#define L1 32
#define L2 128
#define DEC 512
#define MEMD 512
#define TOPN 50

// Scratch (allocation-free rule: __device__ globals)
__device__ float    g_f1[BB * DEC];
__device__ float    g_f2[BB * DEC];
__device__ float    g_doc_score[BB * L1];
__device__ uint32_t g_Wmh[DEC * MEMD / 2];   // Wm as half2 pairs
__device__ float    g_ctxp[BB * L1 * MEMD];  // per-(b,q) partial context

// ============================ helpers =====================================
__device__ __forceinline__ uint32_t smem_u32(const void* p) {
    uint32_t a;
    asm("{ .reg .u64 t; cvta.to.shared.u64 t, %1; cvt.u32.u64 %0, t; }"
        : "=r"(a) : "l"(p));
    return a;
}
#define CP_ASYNC16(dst_u32, src_ptr) \
    asm volatile("cp.async.cg.shared.global [%0], [%1], 16;" \
                 :: "r"(dst_u32), "l"(src_ptr) : "memory")
#define CP_COMMIT() asm volatile("cp.async.commit_group;" ::: "memory")
#define CP_WAIT0()  asm volatile("cp.async.wait_group 0;" ::: "memory")
#define CP_WAIT1()  asm volatile("cp.async.wait_group 1;" ::: "memory")

#define LDSM_X4(R0, R1, R2, R3, addr) \
    asm volatile("ldmatrix.sync.aligned.m8n8.x4.shared.b16 {%0,%1,%2,%3}, [%4];" \
        : "=r"(R0), "=r"(R1), "=r"(R2), "=r"(R3) : "r"(addr))

__device__ __forceinline__ float tanh_hw(float x) {
    float y;
    asm("tanh.approx.f32 %0, %1;" : "=f"(y) : "f"(x));
    return y;
}

__device__ __forceinline__ void mma_f16(float* c, const uint32_t* a, const uint32_t* b) {
    asm volatile(
        "mma.sync.aligned.m16n8k16.row.col.f32.f16.f16.f32 "
        "{%0,%1,%2,%3}, {%4,%5,%6,%7}, {%8,%9}, {%0,%1,%2,%3};"
        : "+f"(c[0]), "+f"(c[1]), "+f"(c[2]), "+f"(c[3])
        : "r"(a[0]), "r"(a[1]), "r"(a[2]), "r"(a[3]), "r"(b[0]), "r"(b[1]));
}

__device__ __forceinline__ uint32_t pack_h2(float x, float y) {
    __half2 h = __floats2half2_rn(x, y);
    return *(uint32_t*)&h;
}

// ---------------------------------------------------------------------------
// Kernel A: f1/f2 bias vectors, zero doc scores, convert Wm -> fp16 pairs.
// ---------------------------------------------------------------------------
__global__ void prep_kernel(const float* __restrict__ dec,
                            const float* __restrict__ topic,
                            const float* __restrict__ Wd,
                            const float* __restrict__ Wt,
                            const float* __restrict__ Wd2,
                            const float* __restrict__ Wt2,
                            const float* __restrict__ Wm) {
    int idx = blockIdx.x * blockDim.x + threadIdx.x;   // 0..8191
    int b = idx >> 9;
    int d = idx & 511;
    if (idx < BB * L1) g_doc_score[idx] = 0.f;

    for (int i = idx; i < DEC * MEMD / 2; i += 8192) {
        float2 v = ((const float2*)Wm)[i];
        g_Wmh[i] = pack_h2(v.x, v.y);
    }

    const float* db  = dec + b * DEC;
    const float* wd  = Wd  + (size_t)d * DEC;
    const float* wd2 = Wd2 + (size_t)d * DEC;

    float f1 = 0.f, f2 = 0.f;
    for (int m = 0; m < DEC; m += 4) {
        float4 dv = *(const float4*)(db + m);
        float4 w1 = *(const float4*)(wd + m);
        float4 w2 = *(const float4*)(wd2 + m);
        f1 += dv.x * w1.x + dv.y * w1.y + dv.z * w1.z + dv.w * w1.w;
        f2 += dv.x * w2.x + dv.y * w2.y + dv.z * w2.z + dv.w * w2.w;
    }
    const float* tb  = topic + b * TOPN;
    const float* wt  = Wt  + (size_t)d * TOPN;
    const float* wt2 = Wt2 + (size_t)d * TOPN;
    for (int t = 0; t < TOPN; ++t) {
        float tv = tb[t];
        f1 += tv * wt[t];
        f2 += tv * wt2[t];
    }
    g_f1[idx] = f1;
    g_f2[idx] = f2;
}

// ---------------------------------------------------------------------------
// Kernel B: word-level fused fp16 GEMM (ldmatrix + mma.m16n8k16) + tanh +
//           Wv-reduce + softmax + partial context from resident A tile.
// One (b,q) per CTA. M=128(w), K=512(m), N=512 d in 2 chunks of 256.
// 8 warps = 2(m) x 4(n); warp tile 64x64.
// B streamed via 3-stage cp.async pipeline (32 chunks of 256 rows x 16 words).
// ---------------------------------------------------------------------------
#define AW 260                      // A row stride in 32-bit words
#define BW 20                       // B row stride in 32-bit words
#define BBUF_BYTES 20480            // 256*BW*4
#define OFF_BBUF 133120             // after A tile (128*260*4)
#define OFF_F    194560             // after 3 B buffers
#define OFF_V    196608
#define OFF_SC   198656
#define OFF_RD   199168
#define SMEM_BYTES 199200

__global__ __launch_bounds__(256, 1)
void word_attn_tc(const float* __restrict__ wmem,   // [B,L1,L2,MEM]
                  const float* __restrict__ Wv,     // [DEC]
                  const int*   __restrict__ wmask,  // [B,L1,L2]
                  float* __restrict__ attn_out) {   // [B,L1,L2]
    extern __shared__ char smem[];
    uint32_t* smA = (uint32_t*)smem;
    float* sF  = (float*)(smem + OFF_F);
    float* sV  = (float*)(smem + OFF_V);
    float* sSc = (float*)(smem + OFF_SC);
    float* sRd = (float*)(smem + OFF_RD);

    const int tid    = threadIdx.x;
    const int wid    = tid >> 5;
    const int lane   = tid & 31;
    const int g      = lane >> 2;
    const int tg     = lane & 3;
    const int warp_m = wid >> 2;       // 0..1
    const int warp_n = wid & 3;        // 0..3
    const int bq     = blockIdx.x;
    const int b      = bq >> 5;

    const uint32_t smA_u32 = smem_u32(smA);
    const uint32_t smB_u32 = smem_u32(smem + OFF_BBUF);

    // per-thread cp.async source/dst indices for a B chunk
    const int ld_row = tid >> 2;       // with i-offset below
    const int ld_q   = tid & 3;

    // ldmatrix per-thread address components
    const int r8   = lane & 7;
    const int hsel = (lane >> 3) & 1;  // +8 rows (A) / k-high (B)
    const int qsel = lane >> 4;        // k-high (A) / +8 rows->nt+1 (B)
    const uint32_t aLm = smA_u32 +
        (((warp_m * 64 + r8 + hsel * 8) * AW) + qsel * 4) * 4;
    const uint32_t bLm = smB_u32 +
        (((warp_n * 64 + r8 + qsel * 8) * BW) + hsel * 4) * 4;

    // ---- issue B chunks 0,1 ----
#pragma unroll
    for (int c = 0; c < 2; ++c) {
#pragma unroll
        for (int i = 0; i < 4; ++i) {
            int idx = tid + 256 * i, row = idx >> 2, q = idx & 3;
            const uint32_t* gp = g_Wmh + (size_t)row * 256 + c * 16 + q * 4;
            CP_ASYNC16(smB_u32 + c * BBUF_BYTES + (row * BW + q * 4) * 4, gp);
        }
        CP_COMMIT();
    }

    // ---- A tile resident load + convert ----
    {
        const float4* A4 = (const float4*)(wmem + (size_t)bq * L2 * MEMD);
#pragma unroll 4
        for (int i = 0; i < 64; ++i) {
            int idx = tid + 256 * i;
            int row = idx >> 7, c = idx & 127;
            float4 v = A4[idx];
            uint32_t* dst = smA + row * AW + c * 2;
            dst[0] = pack_h2(v.x, v.y);
            dst[1] = pack_h2(v.z, v.w);
        }
    }
    for (int i = tid; i < DEC; i += 256) {
        sF[i] = g_f1[b * DEC + i];
        sV[i] = Wv[i];
    }
    if (tid < L2) sSc[tid] = 0.f;
    __syncthreads();   // A tile + sF/sV visible

    for (int ntc = 0; ntc < 2; ++ntc) {
        float acc[4][8][4];
#pragma unroll
        for (int mt = 0; mt < 4; ++mt)
#pragma unroll
            for (int nt = 0; nt < 8; ++nt)
#pragma unroll
                for (int i = 0; i < 4; ++i) acc[mt][nt][i] = 0.f;

        for (int kc = 0; kc < 16; ++kc) {
            const int c = ntc * 16 + kc;
            if (c >= 30) { CP_WAIT0(); } else { CP_WAIT1(); }   // chunk c ready
            __syncthreads();                                    // all past c-1 reads
            if (c + 2 < 32) {                                   // refill (c+2)%3
                const int cn = c + 2;
                const int d0 = (cn >> 4) * 256, kw = (cn & 15) * 16;
                const uint32_t bo = smB_u32 + (cn % 3) * BBUF_BYTES;
#pragma unroll
                for (int i = 0; i < 4; ++i) {
                    int idx = tid + 256 * i, row = idx >> 2, q = idx & 3;
                    const uint32_t* gp = g_Wmh + (size_t)(d0 + row) * 256 + kw + q * 4;
                    CP_ASYNC16(bo + (row * BW + q * 4) * 4, gp);
                }
                CP_COMMIT();
            }

            const uint32_t bufB = bLm + (c % 3) * BBUF_BYTES;
#pragma unroll
            for (int ks = 0; ks < 2; ++ks) {
                uint32_t af[4][4], bf[8][2];
#pragma unroll
                for (int mt = 0; mt < 4; ++mt)
                    LDSM_X4(af[mt][0], af[mt][1], af[mt][2], af[mt][3],
                            aLm + (mt * 16 * AW + kc * 16 + ks * 8) * 4);
#pragma unroll
                for (int p = 0; p < 4; ++p)
                    LDSM_X4(bf[2 * p][0], bf[2 * p][1], bf[2 * p + 1][0], bf[2 * p + 1][1],
                            bufB + (p * 16 * BW + ks * 8) * 4);
#pragma unroll
                for (int mt = 0; mt < 4; ++mt)
#pragma unroll
                    for (int nt = 0; nt < 8; ++nt)
                        mma_f16(acc[mt][nt], af[mt], bf[nt]);
            }
        }

        // ---- epilogue: tanh + Wv dot into per-row partials ----
        float rs[4][2];
#pragma unroll
        for (int mt = 0; mt < 4; ++mt) { rs[mt][0] = 0.f; rs[mt][1] = 0.f; }
#pragma unroll
        for (int mt = 0; mt < 4; ++mt) {
#pragma unroll
            for (int nt = 0; nt < 8; ++nt) {
                const int d0 = ntc * 256 + warp_n * 64 + nt * 8 + 2 * tg;
                float w0 = sV[d0], w1 = sV[d0 + 1];
                float f0 = sF[d0], f1v = sF[d0 + 1];
                rs[mt][0] += tanh_hw(acc[mt][nt][0] + f0) * w0 +
                             tanh_hw(acc[mt][nt][1] + f1v) * w1;
                rs[mt][1] += tanh_hw(acc[mt][nt][2] + f0) * w0 +
                             tanh_hw(acc[mt][nt][3] + f1v) * w1;
            }
        }
#pragma unroll
        for (int ofs = 1; ofs <= 2; ofs <<= 1)
#pragma unroll
            for (int mt = 0; mt < 4; ++mt) {
                rs[mt][0] += __shfl_xor_sync(0xffffffffu, rs[mt][0], ofs);
                rs[mt][1] += __shfl_xor_sync(0xffffffffu, rs[mt][1], ofs);
            }
        if (tg == 0) {
#pragma unroll
            for (int mt = 0; mt < 4; ++mt) {
                atomicAdd(&sSc[warp_m * 64 + mt * 16 + g],     rs[mt][0]);
                atomicAdd(&sSc[warp_m * 64 + mt * 16 + 8 + g], rs[mt][1]);
            }
        }
    }
    __syncthreads();

    // ---- masked softmax over 128 words ----
    float s = -INFINITY;
    if (tid < L2) {
        s = sSc[tid];
        if (wmask[bq * L2 + tid] == 0) s = -INFINITY;
    }
    float m = s;
#pragma unroll
    for (int ofs = 16; ofs; ofs >>= 1)
        m = fmaxf(m, __shfl_xor_sync(0xffffffffu, m, ofs));
    if (lane == 0) sRd[wid] = m;
    __syncthreads();
    float bmax = sRd[0];
#pragma unroll
    for (int i = 1; i < 8; ++i) bmax = fmaxf(bmax, sRd[i]);

    float e = 0.f;
    if (tid < L2 && bmax > -INFINITY) e = expf(s - bmax);
    float t = e;
#pragma unroll
    for (int ofs = 16; ofs; ofs >>= 1)
        t += __shfl_xor_sync(0xffffffffu, t, ofs);
    if (lane == 0) sRd[wid] = t;
    __syncthreads();
    float bsum = 0.f;
#pragma unroll
    for (int i = 0; i < 8; ++i) bsum += sRd[i];

    float attn = 0.f;
    if (tid < L2) {
        attn = (bsum > 0.f) ? e / bsum : 0.f;
        attn_out[bq * L2 + tid] = attn;
    }
    __syncthreads();
    if (tid < L2) sSc[tid] = attn;
    __syncthreads();

    // ---- partial context from resident A tile ----
    float cx = 0.f, cy = 0.f;          // m = 2*tid, 2*tid+1
#pragma unroll 8
    for (int w = 0; w < L2; ++w) {
        float a = sSc[w];
        uint32_t hv = smA[w * AW + tid];
        __half2 h = *(__half2*)&hv;
        float2 f = __half22float2(h);
        cx = fmaf(a, f.x, cx);
        cy = fmaf(a, f.y, cy);
    }
    g_ctxp[bq * MEMD + 2 * tid]     = cx;
    g_ctxp[bq * MEMD + 2 * tid + 1] = cy;
}

// ---------------------------------------------------------------------------
// Kernel C: doc-level partial scores. Grid = 16 b x 8 d-chunks; atomicAdd.
// ---------------------------------------------------------------------------
__global__ void doc_score_kernel(const float* __restrict__ dmem,
                                 const float* __restrict__ Wm2,
                                 const float* __restrict__ Wv2) {
    extern __shared__ float sdoc[];   // 32*512
    const int tid = threadIdx.x;
    const int b   = blockIdx.x >> 3;
    const int dc  = blockIdx.x & 7;

    const float* drow = dmem + (size_t)b * L1 * MEMD;
    for (int i = tid; i < L1 * MEMD; i += 256) sdoc[i] = drow[i];
    __syncthreads();

    const int q    = tid >> 3;
    const int dsub = tid & 7;
    float acc = 0.f;
    for (int k = 0; k < 8; ++k) {
        const int d = dc * 64 + dsub * 8 + k;
        const float4* w = (const float4*)(Wm2 + (size_t)d * MEMD);
        const float4* x = (const float4*)(sdoc + q * MEMD);
        float s0 = 0.f;
#pragma unroll 8
        for (int mm = 0; mm < 128; ++mm) {
            float4 wv = w[mm], xv = x[mm];
            s0 += wv.x * xv.x + wv.y * xv.y + wv.z * xv.z + wv.w * xv.w;
        }
        acc += tanh_hw(s0 + g_f2[b * DEC + d]) * Wv2[d];
    }
    atomicAdd(&g_doc_score[b * L1 + q], acc);
}

// ---------------------------------------------------------------------------
// Kernel D: per-b doc softmax + combine: ctx = sum_q doc_attn*ctxp; resc scale.
// ---------------------------------------------------------------------------
__global__ void combine_kernel(const int* __restrict__ dmask,
                               float* __restrict__ ctx,
                               float* __restrict__ resc) {
    __shared__ float sda[L1];
    const int b = blockIdx.x;       // 16
    const int tid = threadIdx.x;    // 512

    if (tid < L1) {
        float s = g_doc_score[b * L1 + tid];
        if (dmask[b * L1 + tid] == 0) s = -INFINITY;
        float m = s;
#pragma unroll
        for (int ofs = 16; ofs; ofs >>= 1)
            m = fmaxf(m, __shfl_xor_sync(0xffffffffu, m, ofs));
        float e = (m > -INFINITY) ? expf(s - m) : 0.f;
        float sum = e;
#pragma unroll
        for (int ofs = 16; ofs; ofs >>= 1)
            sum += __shfl_xor_sync(0xffffffffu, sum, ofs);
        sda[tid] = (sum > 0.f) ? e / sum : 0.f;
    }
    __syncthreads();

    float acc = 0.f;
#pragma unroll 8
    for (int q = 0; q < L1; ++q)
        acc = fmaf(sda[q], g_ctxp[(b * L1 + q) * MEMD + tid], acc);
    ctx[b * MEMD + tid] = acc;

#pragma unroll
    for (int i = 0; i < 8; ++i) {
        int idx = tid + i * 512;    // 0..4095
        resc[b * (L1 * L2) + idx] *= sda[idx >> 7];
    }
}

// ---------------------------------------------------------------------------
extern "C" void kernel_launch(void* const* d_in, const int* in_sizes, int n_in,
                              void* d_out, int out_size) {
    const float* decoder = (const float*)d_in[0];
    const float* dmem    = (const float*)d_in[1];
    const float* wmem    = (const float*)d_in[2];
    const float* topic   = (const float*)d_in[3];
    const int*   dmask   = (const int*)d_in[4];
    const int*   wmask   = (const int*)d_in[5];
    const float* Wv      = (const float*)d_in[6];
    const float* Wd      = (const float*)d_in[7];
    const float* Wt      = (const float*)d_in[8];
    const float* Wm      = (const float*)d_in[9];
    const float* Wv2     = (const float*)d_in[10];
    const float* Wd2     = (const float*)d_in[11];
    const float* Wt2     = (const float*)d_in[12];
    const float* Wm2     = (const float*)d_in[13];

    float* out  = (float*)d_out;
    float* ctx  = out;                  // context [16,512]
    float* resc = out + BB * MEMD;      // rescaled [16,32,128]

    cudaFuncSetAttribute(word_attn_tc,
                         cudaFuncAttributeMaxDynamicSharedMemorySize, SMEM_BYTES);
    cudaFuncSetAttribute(doc_score_kernel,
                         cudaFuncAttributeMaxDynamicSharedMemorySize, 65536);

    prep_kernel<<<32, 256>>>(decoder, topic, Wd, Wt, Wd2, Wt2, Wm);
    word_attn_tc<<<BB * L1, 256, SMEM_BYTES>>>(wmem, Wv, wmask, resc);
    doc_score_kernel<<<BB * 8, 256, 65536>>>(dmem, Wm2, Wv2);
    combine_kernel<<<BB, 512>>>(dmask, ctx, resc);
}